// round 15
// baseline (speedup 1.0000x reference)
#include <cuda_runtime.h>
#include <cstdint>

// RoiAlign (crop_and_resize, bilinear, extrapolation=0) with 2-level FPN select.
// feat0: [2,256,256,256] f32, feat1: [2,128,128,256] f32, rois: [2,512,5] f32
// out:   [2,512,7,7,256] f32
//
// Mapping: one WARP per pooled cell; each lane handles 8 channels as TWO
// BLOCKED halves: float4 [lane] (channels 0..127) and [lane+32] (128..255).
// Each LDG.128/STG.128 is a fully-contiguous 512B warp access = 4 L1
// wavefronts (vs 8 with interleaved lane*2 layout). 8 independent loads per
// thread (MLP=8). 4 warps per 128-thread block, 12 blocks/SM cap.

#define NUM_B 2
#define NUM_R 512
#define CCH 256
#define POOL 7
#define CELLS_PER_BOX (POOL * POOL)
#define INV_IMG (1.0f / 1024.0f)
#define LVL_THRESH 48.0f

__device__ __forceinline__ float4 lerp4(float4 a, float4 b, float w) {
    return make_float4(fmaf(b.x - a.x, w, a.x),
                       fmaf(b.y - a.y, w, a.y),
                       fmaf(b.z - a.z, w, a.z),
                       fmaf(b.w - a.w, w, a.w));
}

__global__ __launch_bounds__(128, 12) void roialign_kernel(
    const float4* __restrict__ feat0,
    const float4* __restrict__ feat1,
    const float* __restrict__ rois,
    float4* __restrict__ out)
{
    const int warpId = threadIdx.x >> 5;
    const int lane   = threadIdx.x & 31;
    const int cell   = blockIdx.x * 4 + warpId;      // grid sized exactly

    const int box = cell / CELLS_PER_BOX;            // const-div -> mul/shift
    const int pq  = cell - box * CELLS_PER_BOX;      // 0..48
    const int py  = pq / POOL;
    const int px  = pq - py * POOL;
    const int b   = box >> 9;                        // box / 512

    const float* roi = rois + box * 5;
    const float y1 = roi[0];
    const float x1 = roi[1];
    const float y2 = roi[2];
    const float x2 = roi[3];

    const bool lvl1 = ((y2 - y1) > LVL_THRESH) || ((x2 - x1) > LVL_THRESH);
    const float4* __restrict__ img4 = lvl1 ? feat1 : feat0;
    const int HW = lvl1 ? 128 : 256;                 // H == W at both levels
    const float HWm1 = (float)(HW - 1);

    const float ry = (float)py * (1.0f / 6.0f);
    const float rx = (float)px * (1.0f / 6.0f);
    const float ys = (y1 * INV_IMG + ry * (y2 - y1) * INV_IMG) * HWm1;
    const float xs = (x1 * INV_IMG + rx * (x2 - x1) * INV_IMG) * HWm1;

    float4* outp = out + cell * (CCH / 4) + lane;    // blocked halves: +0, +32

    const bool valid = (ys >= 0.0f) && (ys <= HWm1) &&
                       (xs >= 0.0f) && (xs <= HWm1);
    if (!valid) {
        const float4 z = make_float4(0.f, 0.f, 0.f, 0.f);
        outp[0]  = z;
        outp[32] = z;
        return;
    }

    const float y0f = floorf(ys);
    const float x0f = floorf(xs);
    const float wy = ys - y0f;
    const float wx = xs - x0f;

    // valid => y0f,x0f already in [0, HW-1]; only far corner needs clamping
    const int iy0 = (int)y0f;
    const int ix0 = (int)x0f;
    const int iyp = min(iy0 + 1, HW - 1);
    const int ixp = min(ix0 + 1, HW - 1);

    // 32-bit offsets in float4 units
    const int base00 = ((b * HW + iy0) * HW + ix0) * (CCH / 4);
    const int dx = (ixp - ix0) * (CCH / 4);
    const int dy = (iyp - iy0) * HW * (CCH / 4);

    const float4* p = img4 + base00 + lane;
    // 8 independent, fully-coalesced 512B warp loads (MLP=8)
    const float4 a00 = p[0];
    const float4 b00 = p[32];
    const float4 a01 = p[dx];
    const float4 b01 = p[dx + 32];
    const float4 a10 = p[dy];
    const float4 b10 = p[dy + 32];
    const float4 a11 = p[dy + dx];
    const float4 b11 = p[dy + dx + 32];

    const float4 r0 = lerp4(lerp4(a00, a01, wx), lerp4(a10, a11, wx), wy);
    const float4 r1 = lerp4(lerp4(b00, b01, wx), lerp4(b10, b11, wx), wy);

    outp[0]  = r0;
    outp[32] = r1;
}

extern "C" void kernel_launch(void* const* d_in, const int* in_sizes, int n_in,
                              void* d_out, int out_size) {
    const float4* feat0 = (const float4*)d_in[0];
    const float4* feat1 = (const float4*)d_in[1];
    const float* rois   = (const float*)d_in[2];
    float4* out = (float4*)d_out;

    const int n_cells = NUM_B * NUM_R * CELLS_PER_BOX;   // 50176
    const int blocks = n_cells / 4;                      // 12544, exact
    roialign_kernel<<<blocks, 128>>>(feat0, feat1, rois, out);
}

// round 16
// speedup vs baseline: 1.0023x; 1.0023x over previous
#include <cuda_runtime.h>
#include <cstdint>

// RoiAlign (crop_and_resize, bilinear, extrapolation=0) with 2-level FPN select.
// feat0: [2,256,256,256] f32, feat1: [2,128,128,256] f32, rois: [2,512,5] f32
// out:   [2,512,7,7,256] f32
//
// Mapping: one WARP per pooled cell; lane handles 8 channels interleaved
// (float4 at lane*2 and lane*2+1) -- the empirically fastest layout.
// Level (feat0 vs feat1) is warp-uniform -> constexpr-HW template; interior
// cells (no clamp needed) use a single base pointer + immediate offsets for
// all 8 independent LDG.128s.

#define NUM_B 2
#define NUM_R 512
#define CCH 256
#define POOL 7
#define CELLS_PER_BOX (POOL * POOL)
#define INV_IMG (1.0f / 1024.0f)
#define LVL_THRESH 48.0f

__device__ __forceinline__ float4 lerp4(float4 a, float4 b, float w) {
    return make_float4(fmaf(b.x - a.x, w, a.x),
                       fmaf(b.y - a.y, w, a.y),
                       fmaf(b.z - a.z, w, a.z),
                       fmaf(b.w - a.w, w, a.w));
}

template <int HW>
__device__ __forceinline__ void do_cell(
    const float4* __restrict__ img4,
    int b, int py, int px,
    float y1, float x1, float y2, float x2,
    float4* __restrict__ outp, int lane)
{
    constexpr float HWm1 = (float)(HW - 1);
    constexpr int ROW = HW * (CCH / 4);          // float4s per image row

    const float ry = (float)py * (1.0f / 6.0f);
    const float rx = (float)px * (1.0f / 6.0f);
    const float ys = (y1 * INV_IMG + ry * (y2 - y1) * INV_IMG) * HWm1;
    const float xs = (x1 * INV_IMG + rx * (x2 - x1) * INV_IMG) * HWm1;

    const bool valid = (ys >= 0.0f) && (ys <= HWm1) &&
                       (xs >= 0.0f) && (xs <= HWm1);
    if (!valid) {
        const float4 z = make_float4(0.f, 0.f, 0.f, 0.f);
        outp[0] = z;
        outp[1] = z;
        return;
    }

    const float y0f = floorf(ys);
    const float x0f = floorf(xs);
    const float wy = ys - y0f;
    const float wx = xs - x0f;

    const int iy0 = (int)y0f;
    const int ix0 = (int)x0f;

    const int base00 = (b * HW + iy0) * ROW / HW * HW; // folded below; keep simple:
    const float4* p = img4 + ((b * HW + iy0) * HW + ix0) * (CCH / 4) + lane * 2;

    float4 a00, b00, a01, b01, a10, b10, a11, b11;

    if (iy0 < HW - 1 && ix0 < HW - 1) {
        // Interior: all offsets are compile-time immediates off one base.
        a00 = p[0];
        b00 = p[1];
        a01 = p[CCH / 4];
        b01 = p[CCH / 4 + 1];
        a10 = p[ROW];
        b10 = p[ROW + 1];
        a11 = p[ROW + CCH / 4];
        b11 = p[ROW + CCH / 4 + 1];
    } else {
        // Boundary (xs or ys exactly on the last row/col): clamped deltas.
        const int dx = (ix0 < HW - 1) ? (CCH / 4) : 0;
        const int dy = (iy0 < HW - 1) ? ROW : 0;
        a00 = p[0];
        b00 = p[1];
        a01 = p[dx];
        b01 = p[dx + 1];
        a10 = p[dy];
        b10 = p[dy + 1];
        a11 = p[dy + dx];
        b11 = p[dy + dx + 1];
    }

    const float4 r0 = lerp4(lerp4(a00, a01, wx), lerp4(a10, a11, wx), wy);
    const float4 r1 = lerp4(lerp4(b00, b01, wx), lerp4(b10, b11, wx), wy);

    outp[0] = r0;
    outp[1] = r1;
}

__global__ __launch_bounds__(128, 13) void roialign_kernel(
    const float4* __restrict__ feat0,
    const float4* __restrict__ feat1,
    const float* __restrict__ rois,
    float4* __restrict__ out)
{
    const int warpId = threadIdx.x >> 5;
    const int lane   = threadIdx.x & 31;
    const int cell   = blockIdx.x * 4 + warpId;      // grid sized exactly

    const int box = cell / CELLS_PER_BOX;            // const-div -> mul/shift
    const int pq  = cell - box * CELLS_PER_BOX;      // 0..48
    const int py  = pq / POOL;
    const int px  = pq - py * POOL;
    const int b   = box >> 9;                        // box / 512

    const float* roi = rois + box * 5;
    const float y1 = roi[0];
    const float x1 = roi[1];
    const float y2 = roi[2];
    const float x2 = roi[3];

    float4* outp = out + cell * (CCH / 4) + lane * 2;

    const bool lvl1 = ((y2 - y1) > LVL_THRESH) || ((x2 - x1) > LVL_THRESH);
    if (lvl1) {
        do_cell<128>(feat1, b, py, px, y1, x1, y2, x2, outp, lane);
    } else {
        do_cell<256>(feat0, b, py, px, y1, x1, y2, x2, outp, lane);
    }
}

extern "C" void kernel_launch(void* const* d_in, const int* in_sizes, int n_in,
                              void* d_out, int out_size) {
    const float4* feat0 = (const float4*)d_in[0];
    const float4* feat1 = (const float4*)d_in[1];
    const float* rois   = (const float*)d_in[2];
    float4* out = (float4*)d_out;

    const int n_cells = NUM_B * NUM_R * CELLS_PER_BOX;   // 50176
    const int blocks = n_cells / 4;                      // 12544, exact
    roialign_kernel<<<blocks, 128>>>(feat0, feat1, rois, out);
}

// round 17
// speedup vs baseline: 1.0932x; 1.0907x over previous
#include <cuda_runtime.h>
#include <cstdint>

// RoiAlign (crop_and_resize, bilinear, extrapolation=0) with 2-level FPN select.
// feat0: [2,256,256,256] f32, feat1: [2,128,128,256] f32, rois: [2,512,5] f32
// out:   [2,512,7,7,256] f32
//
// Mapping: one WARP per (box, py, px-pair, channel-half). The two cells of a
// pair share their bilinear y-rows (same ys) and often share x corner columns;
// warp-uniform compares select a static 4-, 6-, or 8-load path (all loads
// independent -> full MLP, no serial reuse chain). Lane = one float4
// (4 channels); half selects channels 0..127 / 128..255.

#define NUM_B 2
#define NUM_R 512
#define CCH 256
#define POOL 7
#define CELLS_PER_BOX (POOL * POOL)
#define INV_IMG (1.0f / 1024.0f)
#define LVL_THRESH 48.0f

__device__ __forceinline__ float4 lerp4(float4 a, float4 b, float w) {
    return make_float4(fmaf(b.x - a.x, w, a.x),
                       fmaf(b.y - a.y, w, a.y),
                       fmaf(b.z - a.z, w, a.z),
                       fmaf(b.w - a.w, w, a.w));
}

__device__ __forceinline__ float4 bilerp(float4 t0, float4 t1, float4 b0, float4 b1,
                                         float wx, float wy) {
    return lerp4(lerp4(t0, t1, wx), lerp4(b0, b1, wx), wy);
}

__global__ __launch_bounds__(128, 8) void roialign_kernel(
    const float4* __restrict__ feat0,
    const float4* __restrict__ feat1,
    const float* __restrict__ rois,
    float4* __restrict__ out,
    int n_tasks)
{
    const int warpId = threadIdx.x >> 5;
    const int lane   = threadIdx.x & 31;
    const int task   = blockIdx.x * 4 + warpId;
    if (task >= n_tasks) return;

    // task = (((box*7 + py)*4 + g)*2 + half)
    const int half = task & 1;
    const int t2   = task >> 1;
    const int g    = t2 & 3;              // px-pair group: px0 = 2g; g==3 -> single cell
    const int t3   = t2 >> 2;             // box*7 + py
    const int box  = t3 / POOL;
    const int py   = t3 - box * POOL;
    const int b    = box >> 9;
    const int px0  = g * 2;
    const bool has2 = (g < 3);

    const float* roi = rois + box * 5;
    const float y1 = roi[0];
    const float x1 = roi[1];
    const float y2 = roi[2];
    const float x2 = roi[3];

    const bool lvl1 = ((y2 - y1) > LVL_THRESH) || ((x2 - x1) > LVL_THRESH);
    const float4* __restrict__ img4 = lvl1 ? feat1 : feat0;
    const int HW = lvl1 ? 128 : 256;
    const float HWm1 = (float)(HW - 1);

    const int ch = half * 32 + lane;      // float4 index within pixel
    float4* outp = out + (box * CELLS_PER_BOX + py * POOL + px0) * (CCH / 4) + ch;
    const float4 z = make_float4(0.f, 0.f, 0.f, 0.f);

    // ---- y sample (shared by both cells; identical arithmetic to passing kernels)
    const float ry = (float)py * (1.0f / 6.0f);
    const float ys = (y1 * INV_IMG + ry * (y2 - y1) * INV_IMG) * HWm1;
    if (!(ys >= 0.0f && ys <= HWm1)) {
        outp[0] = z;
        if (has2) outp[CCH / 4] = z;
        return;
    }
    const float y0f = floorf(ys);
    const float wy  = ys - y0f;
    const int iy0 = (int)y0f;
    const int iyp = min(iy0 + 1, HW - 1);

    const float4* __restrict__ r0p = img4 + ((b * HW + iy0) * HW) * (CCH / 4) + ch;
    const float4* __restrict__ r1p = img4 + ((b * HW + iyp) * HW) * (CCH / 4) + ch;

    // ---- x samples for the two cells
    const float rx0 = (float)px0 * (1.0f / 6.0f);
    const float rx1 = (float)(px0 + 1) * (1.0f / 6.0f);
    const float xs0 = (x1 * INV_IMG + rx0 * (x2 - x1) * INV_IMG) * HWm1;
    const float xs1 = (x1 * INV_IMG + rx1 * (x2 - x1) * INV_IMG) * HWm1;
    const bool vx0 = (xs0 >= 0.0f) && (xs0 <= HWm1);
    const bool vx1 = has2 && (xs1 >= 0.0f) && (xs1 <= HWm1);

    if (vx0 && vx1) {
        const float x0f0 = floorf(xs0);
        const float x0f1 = floorf(xs1);
        const float wx0 = xs0 - x0f0;
        const float wx1 = xs1 - x0f1;
        const int ix00 = (int)x0f0;
        const int ix01 = (int)x0f1;
        const int ixp0 = min(ix00 + 1, HW - 1);
        const int ixp1 = min(ix01 + 1, HW - 1);

        float4 o0, o1;
        if (ix01 == ix00) {
            // 2 distinct columns: both cells use the same 4 corners
            const float4 A = r0p[ix00 * (CCH / 4)];
            const float4 Bv = r0p[ixp0 * (CCH / 4)];
            const float4 C = r1p[ix00 * (CCH / 4)];
            const float4 D = r1p[ixp0 * (CCH / 4)];
            o0 = bilerp(A, Bv, C, D, wx0, wy);
            o1 = bilerp(A, Bv, C, D, wx1, wy);
        } else if (ix01 == ixp0) {
            // 3 distinct columns: middle column shared
            const float4 A = r0p[ix00 * (CCH / 4)];
            const float4 Bv = r0p[ix01 * (CCH / 4)];
            const float4 E = r0p[ixp1 * (CCH / 4)];
            const float4 C = r1p[ix00 * (CCH / 4)];
            const float4 D = r1p[ix01 * (CCH / 4)];
            const float4 F = r1p[ixp1 * (CCH / 4)];
            o0 = bilerp(A, Bv, C, D, wx0, wy);
            o1 = bilerp(Bv, E, D, F, wx1, wy);
        } else {
            // 4 distinct columns: fully independent
            const float4 A = r0p[ix00 * (CCH / 4)];
            const float4 Bv = r0p[ixp0 * (CCH / 4)];
            const float4 C = r1p[ix00 * (CCH / 4)];
            const float4 D = r1p[ixp0 * (CCH / 4)];
            const float4 E = r0p[ix01 * (CCH / 4)];
            const float4 F = r0p[ixp1 * (CCH / 4)];
            const float4 G = r1p[ix01 * (CCH / 4)];
            const float4 Hh = r1p[ixp1 * (CCH / 4)];
            o0 = bilerp(A, Bv, C, D, wx0, wy);
            o1 = bilerp(E, F, G, Hh, wx1, wy);
        }
        outp[0] = o0;
        outp[CCH / 4] = o1;
    } else {
        // Rare edge path: handle each cell independently
        if (vx0) {
            const float x0f0 = floorf(xs0);
            const float wx0 = xs0 - x0f0;
            const int ix00 = (int)x0f0;
            const int ixp0 = min(ix00 + 1, HW - 1);
            const float4 A = r0p[ix00 * (CCH / 4)];
            const float4 Bv = r0p[ixp0 * (CCH / 4)];
            const float4 C = r1p[ix00 * (CCH / 4)];
            const float4 D = r1p[ixp0 * (CCH / 4)];
            outp[0] = bilerp(A, Bv, C, D, wx0, wy);
        } else {
            outp[0] = z;
        }
        if (has2) {
            if (vx1) {
                const float x0f1 = floorf(xs1);
                const float wx1 = xs1 - x0f1;
                const int ix01 = (int)x0f1;
                const int ixp1 = min(ix01 + 1, HW - 1);
                const float4 E = r0p[ix01 * (CCH / 4)];
                const float4 F = r0p[ixp1 * (CCH / 4)];
                const float4 G = r1p[ix01 * (CCH / 4)];
                const float4 Hh = r1p[ixp1 * (CCH / 4)];
                outp[CCH / 4] = bilerp(E, F, G, Hh, wx1, wy);
            } else {
                outp[CCH / 4] = z;
            }
        }
    }
}

extern "C" void kernel_launch(void* const* d_in, const int* in_sizes, int n_in,
                              void* d_out, int out_size) {
    const float4* feat0 = (const float4*)d_in[0];
    const float4* feat1 = (const float4*)d_in[1];
    const float* rois   = (const float*)d_in[2];
    float4* out = (float4*)d_out;

    // tasks: 1024 boxes * 7 py * 4 px-groups * 2 channel-halves
    const int n_tasks = NUM_B * NUM_R * POOL * 4 * 2;   // 57344
    const int blocks = n_tasks / 4;                     // 14336, exact
    roialign_kernel<<<blocks, 128>>>(feat0, feat1, rois, out, n_tasks);
}